// round 3
// baseline (speedup 1.0000x reference)
#include <cuda_runtime.h>

// HorizontalWidthTokenPyramid: x [32, 256, 32, 16, 16] f32
//   -> out [N*C*S, 31, 4] f32
// Per (n,c,s) 16x16 slice: for b in {16,8,4,2,1}: bin H into b bins
// (mean+max per column), then pool W 16->4 tokens (mean+max). Concat -> 31.
//
// Mapping: 8 threads/slice; thread pair p owns token p (cols 4p..4p+3),
// each thread owns 2 of those columns (one float2 per row -> 64B coalesced
// per slice-row). Width combine across the pair via shfl_xor(1). Pyramid
// folded progressively -> ~16 floats of accumulator state -> <=42 regs ->
// 6 blocks/SM (48 warps) vs 4 before.

namespace {

constexpr int THREADS          = 256;
constexpr int SLICES_PER_BLOCK = 32;        // THREADS / 8
constexpr int OUT_PER_SLICE    = 31 * 4;    // 124
constexpr int SLICE_FLOATS     = 256;       // 16*16
constexpr int SMEM_FLOATS      = SLICES_PER_BLOCK * OUT_PER_SLICE;  // 3968

// Combine a 2-column partial (zs = z0+z1, zm = max(z0,z1)) with the partner
// lane's 2 columns -> full 4-column token: 0.25*sum(z) + max(z).
__device__ __forceinline__ float tok2(float zs, float zm) {
    zs += __shfl_xor_sync(0xFFFFFFFFu, zs, 1);
    zm = fmaxf(zm, __shfl_xor_sync(0xFFFFFFFFu, zm, 1));
    return 0.25f * zs + zm;
}

// bin with per-column (sum, max) over the H-span: z_c = inv*s_c + m_c
__device__ __forceinline__ float tok_bin(float s0, float s1, float m0, float m1,
                                         float inv) {
    const float z0 = inv * s0 + m0;
    const float z1 = inv * s1 + m1;
    return tok2(z0 + z1, fmaxf(z0, z1));
}

__global__ __launch_bounds__(THREADS, 6)
void hwtp_kernel(const float2* __restrict__ x2, float* __restrict__ out) {
    __shared__ float sm[SMEM_FLOATS];   // 15872 B

    const int tid  = threadIdx.x;
    const int sl   = tid >> 3;          // local slice 0..31
    const int h    = tid & 7;
    const int pair = h >> 1;            // token 0..3
    const int half = h & 1;             // which 2 columns of the token

    const long slice = (long)blockIdx.x * SLICES_PER_BLOCK + sl;
    // float2 index within slice for row r: r*8 + pair*2 + half
    const float2* p = x2 + slice * (SLICE_FLOATS / 2) + (pair * 2 + half);

    float* o = &sm[sl * OUT_PER_SLICE + pair];   // write o[bin*4]

    // running (sum, max) per owned column, per pyramid level
    float s4a, s4b, m4a, m4b;   // level b=4  (4 rows)
    float s2a, s2b, m2a, m2b;   // level b=2  (8 rows)
    float s1a, s1b, m1a, m1b;   // level b=1  (16 rows)

    #pragma unroll
    for (int i = 0; i < 8; ++i) {               // row pair: rows 2i, 2i+1
        const float2 v0 = __ldcs(&p[(2 * i) * 8]);
        const float2 v1 = __ldcs(&p[(2 * i + 1) * 8]);

        // level b=16 (bin of 1 row): z = 2*v
        {
            const float t0 = tok2(2.0f * (v0.x + v0.y), 2.0f * fmaxf(v0.x, v0.y));
            const float t1 = tok2(2.0f * (v1.x + v1.y), 2.0f * fmaxf(v1.x, v1.y));
            if (half == 0) {
                o[(2 * i) * 4]     = t0;
                o[(2 * i + 1) * 4] = t1;
            }
        }

        // pair = level b=8 bin
        const float psa = v0.x + v1.x, psb = v0.y + v1.y;
        const float pma = fmaxf(v0.x, v1.x), pmb = fmaxf(v0.y, v1.y);
        {
            const float t = tok_bin(psa, psb, pma, pmb, 0.5f);
            if (half == 0) o[(16 + i) * 4] = t;
        }

        // fold into level b=4
        if ((i & 1) == 0) {
            s4a = psa; s4b = psb; m4a = pma; m4b = pmb;
        } else {
            s4a += psa; s4b += psb;
            m4a = fmaxf(m4a, pma); m4b = fmaxf(m4b, pmb);
            const int j = i >> 1;
            const float t = tok_bin(s4a, s4b, m4a, m4b, 0.25f);
            if (half == 0) o[(24 + j) * 4] = t;

            // fold into level b=2
            if ((j & 1) == 0) {
                s2a = s4a; s2b = s4b; m2a = m4a; m2b = m4b;
            } else {
                s2a += s4a; s2b += s4b;
                m2a = fmaxf(m2a, m4a); m2b = fmaxf(m2b, m4b);
                const int t2i = j >> 1;
                const float t = tok_bin(s2a, s2b, m2a, m2b, 0.125f);
                if (half == 0) o[(28 + t2i) * 4] = t;

                // fold into level b=1
                if (t2i == 0) {
                    s1a = s2a; s1b = s2b; m1a = m2a; m1b = m2b;
                } else {
                    s1a += s2a; s1b += s2b;
                    m1a = fmaxf(m1a, m2a); m1b = fmaxf(m1b, m2b);
                    const float tf = tok_bin(s1a, s1b, m1a, m1b, 0.0625f);
                    if (half == 0) o[30 * 4] = tf;
                }
            }
        }
    }

    __syncthreads();

    // Coalesced streaming flush: 3968 contiguous floats per block
    float* ob = out + (long)blockIdx.x * SMEM_FLOATS;
    #pragma unroll
    for (int i = tid; i < SMEM_FLOATS; i += THREADS)
        __stcs(&ob[i], sm[i]);
}

}  // namespace

extern "C" void kernel_launch(void* const* d_in, const int* in_sizes, int n_in,
                              void* d_out, int out_size) {
    const float* x = (const float*)d_in[0];
    float* out = (float*)d_out;

    const long total_floats = (long)in_sizes[0];         // 67,108,864
    const long slices = total_floats / SLICE_FLOATS;     // 262,144
    const int blocks = (int)(slices / SLICES_PER_BLOCK); // 8192

    hwtp_kernel<<<blocks, THREADS>>>(reinterpret_cast<const float2*>(x), out);
}